// round 14
// baseline (speedup 1.0000x reference)
#include <cuda_runtime.h>
#include <cstdint>

#define Bb 2
#define Ss 2048
#define Dd 768
#define Hh 12
#define WIN 64

// ---------------- scratch (no allocations allowed) ----------------
__device__ float    g_qkv[(size_t)Bb * Ss * 3 * Dd];   // [B*S, 2304]
__device__ float    g_q[(size_t)Bb * Hh * Ss * 64];    // [B,H,S,64]
__device__ float    g_k[(size_t)Bb * Hh * Ss * 64];
__device__ float    g_v[(size_t)Bb * Hh * Ss * 64];
__device__ unsigned g_af1[(size_t)Bb * Ss * Dd];       // hidden, fragment order (tf32)
__device__ unsigned g_af2[(size_t)Bb * Ss * Dd];       // attn out, fragment order (tf32)
__device__ unsigned g_bf1[(size_t)3 * Dd * Dd];        // Wqkv, fragment order (tf32)
__device__ unsigned g_bf2[(size_t)Dd * Dd];            // Wo, fragment order (tf32)

__device__ __forceinline__ unsigned f2tf(float f) {
    unsigned u;
    asm("cvt.rna.tf32.f32 %0, %1;" : "=r"(u) : "f"(f));
    return u;
}

// ============ one-shot reformat: A [M,K] row-major -> fragment order ============
__global__ void fmt_a(const float* __restrict__ A, uint4* __restrict__ dst, int K)
{
    int idx = blockIdx.x * blockDim.x + threadIdx.x;
    int kch = K >> 5;
    int lane = idx & 31;
    int mt   = (idx >> 5) & 7;
    int kt   = (idx >> 8) & 3;
    int kc   = (idx >> 10) % kch;
    int bm   = idx / (kch << 10);
    int g = lane >> 2, r = lane & 3;
    int row = bm * 128 + mt * 16 + g;
    int col = kc * 32 + kt * 8 + r;
    const float* p = A + (size_t)row * K + col;
    dst[idx] = make_uint4(f2tf(p[0]), f2tf(p[(size_t)8 * K]),
                          f2tf(p[4]), f2tf(p[(size_t)8 * K + 4]));
}

// ============ one-shot reformat: B [N,K] row-major -> fragment order ============
__global__ void fmt_b(const float* __restrict__ W, uint2* __restrict__ dst, int K)
{
    int idx = blockIdx.x * blockDim.x + threadIdx.x;
    int kch = K >> 5;
    int lane = idx & 31;
    int kt   = (idx >> 5) & 3;
    int nt   = (idx >> 7) & 7;
    int kc   = (idx >> 10) % kch;
    int bn   = idx / (kch << 10);
    int g = lane >> 2, r = lane & 3;
    int nrow = bn * 64 + nt * 8 + g;
    int col  = kc * 32 + kt * 8 + r;
    const float* p = W + (size_t)nrow * K + col;
    dst[idx] = make_uint2(f2tf(p[0]), f2tf(p[4]));
}

// ================= tf32 tensor-core GEMM, direct-from-global fragments =================
__device__ __forceinline__ void mma8(float* d, const uint4& a, const uint2& b) {
    asm volatile(
        "mma.sync.aligned.m16n8k8.row.col.f32.tf32.tf32.f32 "
        "{%0,%1,%2,%3}, {%4,%5,%6,%7}, {%8,%9}, {%0,%1,%2,%3};\n"
        : "+f"(d[0]), "+f"(d[1]), "+f"(d[2]), "+f"(d[3])
        : "r"(a.x), "r"(a.y), "r"(a.z), "r"(a.w), "r"(b.x), "r"(b.y));
}

__global__ __launch_bounds__(256, 2)
void tgemm_d(const uint4* __restrict__ Af, const uint2* __restrict__ Bf,
             float* __restrict__ C, int N, int K)
{
    const int t    = threadIdx.x;
    const int w    = t >> 5;
    const int lane = t & 31;
    const int g    = lane >> 2;
    const int r    = lane & 3;
    const int wm   = w & 3;
    const int wn   = w >> 2;
    const int bm   = blockIdx.y, bn = blockIdx.x;
    const int kch  = K >> 5;
    const int nks  = K >> 3;

    const uint4* Ap = Af + (size_t)bm * kch * 1024 + (wm * 2) * 32 + lane;
    const uint2* Bp = Bf + (size_t)(bn * 2 + wn) * kch * 1024 + lane;

    float c[2][8][4];
#pragma unroll
    for (int i = 0; i < 2; i++)
#pragma unroll
        for (int j = 0; j < 8; j++)
#pragma unroll
            for (int e = 0; e < 4; e++) c[i][j][e] = 0.f;

    uint4 a0 = Ap[0], a1 = Ap[32];
    uint2 b[8];
#pragma unroll
    for (int j = 0; j < 8; j++) b[j] = Bp[j * 128];

    for (int ks = 0; ks < nks - 1; ks++) {
        int ks1 = ks + 1;
        const uint4* An = Ap + (size_t)ks1 * 256;
        const uint2* Bn = Bp + ((ks1 >> 2) * 1024 + (ks1 & 3) * 32);
        uint4 na0 = An[0];
        uint4 na1 = An[32];
        uint2 nb[8];
#pragma unroll
        for (int j = 0; j < 8; j++) nb[j] = Bn[j * 128];

#pragma unroll
        for (int j = 0; j < 8; j++) {
            mma8(c[0][j], a0, b[j]);
            mma8(c[1][j], a1, b[j]);
        }

        a0 = na0; a1 = na1;
#pragma unroll
        for (int j = 0; j < 8; j++) b[j] = nb[j];
    }
#pragma unroll
    for (int j = 0; j < 8; j++) {
        mma8(c[0][j], a0, b[j]);
        mma8(c[1][j], a1, b[j]);
    }

    float* Cp = C + (size_t)(bm * 128) * N + bn * 128 + wn * 64;
#pragma unroll
    for (int i = 0; i < 2; i++) {
#pragma unroll
        for (int j = 0; j < 8; j++) {
            int row = (wm * 2 + i) * 16 + g;
            int col = j * 8 + r * 2;
            *(float2*)(Cp + (size_t)row * N + col) =
                make_float2(c[i][j][0], c[i][j][1]);
            *(float2*)(Cp + (size_t)(row + 8) * N + col) =
                make_float2(c[i][j][2], c[i][j][3]);
        }
    }
}

// ---------------- RoPE + split into Q,K,V [B,H,S,64] ----------------
__global__ void rope_split(const float* __restrict__ qkv)
{
    int idx = blockIdx.x * blockDim.x + threadIdx.x;
    if (idx >= Bb * Ss * Hh * 32) return;
    int i  = idx & 31;
    int t2 = idx >> 5;
    int h  = t2 % Hh;
    int t3 = t2 / Hh;
    int s  = t3 % Ss;
    int b  = t3 / Ss;

    float inv = exp2f(-(float)(2 * i) * (1.0f / 64.f) * 13.287712379549449f);
    float fr  = (float)s * inv;
    float cs, sn;
    sincosf(fr, &sn, &cs);

    size_t base = ((size_t)(b * Ss + s)) * (3 * Dd) + h * 64 + i;
    float q1 = qkv[base],        q2 = qkv[base + 32];
    float k1 = qkv[base + Dd],   k2 = qkv[base + Dd + 32];
    float v1 = qkv[base + 2*Dd], v2 = qkv[base + 2*Dd + 32];

    size_t ob = ((size_t)((b * Hh + h) * Ss + s)) * 64 + i;
    g_q[ob]      = q1 * cs - q2 * sn;
    g_q[ob + 32] = q2 * cs + q1 * sn;
    g_k[ob]      = k1 * cs - k2 * sn;
    g_k[ob + 32] = k2 * cs + k1 * sn;
    g_v[ob]      = v1;
    g_v[ob + 32] = v2;
}

// ---------------- sliding-window attention (4 rows per K/V load) ----------------
#define QT 64
#define KT 192          // QT + 2*WIN
#define KST 68          // smem row stride (floats)

__global__ __launch_bounds__(256, 1)
void attn_kernel()
{
    extern __shared__ float sm[];
    float* Ks = sm;                      // [KT][KST]
    float* Vs = sm + KT * KST;           // [KT][KST]
    float* Qs = sm + 2 * KT * KST;       // [QT][64]

    const int t  = threadIdx.x;
    const int qt = blockIdx.x * QT;
    const int h  = blockIdx.y, b = blockIdx.z;
    const float* Kg = g_k + (size_t)((b * Hh + h) * Ss) * 64;
    const float* Vg = g_v + (size_t)((b * Hh + h) * Ss) * 64;
    const float* Qg = g_q + (size_t)((b * Hh + h) * Ss) * 64;

    for (int i = t; i < KT * 16; i += 256) {
        int row = i >> 4, c = (i & 15) * 4;
        int g = qt - WIN + row;
        float4 kv = make_float4(0.f, 0.f, 0.f, 0.f);
        float4 vv = make_float4(0.f, 0.f, 0.f, 0.f);
        if (g >= 0 && g < Ss) {
            kv = *(const float4*)(Kg + (size_t)g * 64 + c);
            vv = *(const float4*)(Vg + (size_t)g * 64 + c);
        }
        *(float4*)&Ks[row * KST + c] = kv;
        *(float4*)&Vs[row * KST + c] = vv;
    }
    for (int i = t; i < QT * 16; i += 256) {
        int row = i >> 4, c = (i & 15) * 4;
        float4 qv = *(const float4*)(Qg + (size_t)(qt + row) * 64 + c);
        qv.x *= 0.125f; qv.y *= 0.125f; qv.z *= 0.125f; qv.w *= 0.125f;
        *(float4*)&Qs[row * 64 + c] = qv;
    }
    __syncthreads();

    const int w = t >> 5, lane = t & 31;
#pragma unroll
    for (int gi = 0; gi < 2; gi++) {
        const int ql0 = w * 8 + gi * 4;          // 4 consecutive rows, 4-aligned
        float m[4], l[4], acc0[4], acc1[4], p[4];
#pragma unroll
        for (int i = 0; i < 4; i++) { m[i] = -1e30f; l[i] = 0.f; acc0[i] = 0.f; acc1[i] = 0.f; }

        const int cbase = (ql0 >> 5) * 32;       // same for all 4 rows (group is 4-aligned)
#pragma unroll
        for (int c = 0; c < 5; c++) {
            int j0 = cbase + c * 32;
            int jl = j0 + lane;
            int g  = qt - WIN + jl;

            // ---- 4 dots per K load ----
            float sum[4] = {0.f, 0.f, 0.f, 0.f};
            const float4* kr = (const float4*)&Ks[jl * KST];
            const float4* qr = (const float4*)&Qs[ql0 * 64];
#pragma unroll
            for (int d = 0; d < 16; d++) {
                float4 k4 = kr[d];
#pragma unroll
                for (int i = 0; i < 4; i++) {
                    float4 q4 = qr[i * 16 + d];
                    sum[i] += q4.x * k4.x + q4.y * k4.y + q4.z * k4.z + q4.w * k4.w;
                }
            }

            // ---- online softmax state per row ----
#pragma unroll
            for (int i = 0; i < 4; i++) {
                int ql = ql0 + i;
                bool valid = (g >= 0) && (g < Ss) && (jl >= ql) && (jl <= ql + 2 * WIN);
                float s = valid ? sum[i] : -3.0e38f;

                float cm = s;
#pragma unroll
                for (int o = 16; o; o >>= 1) cm = fmaxf(cm, __shfl_xor_sync(0xffffffffu, cm, o));
                float nm   = fmaxf(m[i], cm);
                float corr = __expf(m[i] - nm);
                p[i] = __expf(s - nm);
                float ps = p[i];
#pragma unroll
                for (int o = 16; o; o >>= 1) ps += __shfl_xor_sync(0xffffffffu, ps, o);
                l[i] = l[i] * corr + ps;
                acc0[i] *= corr; acc1[i] *= corr;
                m[i] = nm;
            }

            // ---- V accumulation: one V load serves 4 rows ----
#pragma unroll
            for (int j = 0; j < 32; j++) {
                float v0 = Vs[(j0 + j) * KST + lane];
                float v1 = Vs[(j0 + j) * KST + lane + 32];
#pragma unroll
                for (int i = 0; i < 4; i++) {
                    float pj = __shfl_sync(0xffffffffu, p[i], j);
                    acc0[i] += pj * v0;
                    acc1[i] += pj * v1;
                }
            }
        }

        // ---- fragment-order tf32 stores into g_af2 ----
#pragma unroll
        for (int i = 0; i < 4; i++) {
            float invl = 1.f / l[i];
            int row = b * Ss + qt + ql0 + i;
            int bm = row >> 7, mt = (row >> 4) & 7, gg = row & 7, hi = (row >> 3) & 1;
            int kc  = (h * 64 + lane) >> 5;
            int kt  = (lane >> 3) & 3;
            int rr  = lane & 3;
            int ch  = (lane >> 2) & 1;
            int reg = hi + 2 * ch;
            size_t off = ((size_t)bm * (Dd / 32) + kc) * 4096
                       + (size_t)((kt * 8 + mt) * 32 + (gg * 4 + rr)) * 4 + reg;
            g_af2[off]        = f2tf(acc0[i] * invl);
            g_af2[off + 4096] = f2tf(acc1[i] * invl);
        }
    }
}

// ---------------- launch ----------------
extern "C" void kernel_launch(void* const* d_in, const int* in_sizes, int n_in,
                              void* d_out, int out_size)
{
    const float* hidden = (const float*)d_in[0];   // [B,S,D]
    const float* Wqkv   = (const float*)d_in[1];   // [3D, D]
    const float* Wo     = (const float*)d_in[2];   // [D, D]
    float* out = (float*)d_out;

    float *qkv;
    unsigned *af1, *af2, *bf1, *bf2;
    cudaGetSymbolAddress((void**)&qkv, g_qkv);
    cudaGetSymbolAddress((void**)&af1, g_af1);
    cudaGetSymbolAddress((void**)&af2, g_af2);
    cudaGetSymbolAddress((void**)&bf1, g_bf1);
    cudaGetSymbolAddress((void**)&bf2, g_bf2);

    // 0) one-shot reformats into fragment order (tf32)
    fmt_a<<<(Bb * Ss * Dd / 4) / 256, 256>>>(hidden, (uint4*)af1, Dd);
    fmt_b<<<(3 * Dd * Dd / 2) / 256, 256>>>(Wqkv, (uint2*)bf1, Dd);
    fmt_b<<<(Dd * Dd / 2) / 256, 256>>>(Wo, (uint2*)bf2, Dd);

    // 1) QKV projection: [4096,768] x [2304,768]^T -> [4096,2304]
    tgemm_d<<<dim3(3 * Dd / 128, Bb * Ss / 128), 256>>>((const uint4*)af1,
                                                        (const uint2*)bf1,
                                                        qkv, 3 * Dd, Dd);
    // 2) RoPE + split
    rope_split<<<(Bb * Ss * Hh * 32 + 255) / 256, 256>>>(qkv);

    // 3) sliding-window attention -> g_af2 (fragment order)
    const int SMEM = (2 * KT * KST + QT * 64) * (int)sizeof(float);
    cudaFuncSetAttribute(attn_kernel, cudaFuncAttributeMaxDynamicSharedMemorySize, SMEM);
    attn_kernel<<<dim3(Ss / QT, Hh, Bb), 256, SMEM>>>();

    // 4) output projection: [4096,768] x [768,768]^T -> [4096,768]
    tgemm_d<<<dim3(Dd / 128, Bb * Ss / 128), 256>>>((const uint4*)af2,
                                                    (const uint2*)bf2,
                                                    out, Dd, Dd);
}

// round 15
// speedup vs baseline: 1.1829x; 1.1829x over previous
#include <cuda_runtime.h>
#include <cstdint>

#define Bb 2
#define Ss 2048
#define Dd 768
#define Hh 12
#define WIN 64

// ---------------- scratch (no allocations allowed) ----------------
__device__ float    g_qkv[(size_t)Bb * Ss * 3 * Dd];   // [B*S, 2304]
__device__ float    g_q[(size_t)Bb * Hh * Ss * 64];    // [B,H,S,64]
__device__ float    g_k[(size_t)Bb * Hh * Ss * 64];
__device__ float    g_v[(size_t)Bb * Hh * Ss * 64];
__device__ unsigned g_af1[(size_t)Bb * Ss * Dd];       // hidden, fragment order (tf32)
__device__ unsigned g_af2[(size_t)Bb * Ss * Dd];       // attn out, fragment order (tf32)
__device__ unsigned g_bf1[(size_t)3 * Dd * Dd];        // Wqkv, fragment order (tf32)
__device__ unsigned g_bf2[(size_t)Dd * Dd];            // Wo, fragment order (tf32)

__device__ __forceinline__ unsigned f2tf(float f) {
    unsigned u;
    asm("cvt.rna.tf32.f32 %0, %1;" : "=r"(u) : "f"(f));
    return u;
}

// ============ one-shot reformat: A [M,K] row-major -> fragment order ============
__global__ void fmt_a(const float* __restrict__ A, uint4* __restrict__ dst, int K)
{
    int idx = blockIdx.x * blockDim.x + threadIdx.x;
    int kch = K >> 5;
    int lane = idx & 31;
    int mt   = (idx >> 5) & 7;
    int kt   = (idx >> 8) & 3;
    int kc   = (idx >> 10) % kch;
    int bm   = idx / (kch << 10);
    int g = lane >> 2, r = lane & 3;
    int row = bm * 128 + mt * 16 + g;
    int col = kc * 32 + kt * 8 + r;
    const float* p = A + (size_t)row * K + col;
    dst[idx] = make_uint4(f2tf(p[0]), f2tf(p[(size_t)8 * K]),
                          f2tf(p[4]), f2tf(p[(size_t)8 * K + 4]));
}

// ============ one-shot reformat: B [N,K] row-major -> fragment order ============
__global__ void fmt_b(const float* __restrict__ W, uint2* __restrict__ dst, int K)
{
    int idx = blockIdx.x * blockDim.x + threadIdx.x;
    int kch = K >> 5;
    int lane = idx & 31;
    int kt   = (idx >> 5) & 3;
    int nt   = (idx >> 7) & 7;
    int kc   = (idx >> 10) % kch;
    int bn   = idx / (kch << 10);
    int g = lane >> 2, r = lane & 3;
    int nrow = bn * 64 + nt * 8 + g;
    int col  = kc * 32 + kt * 8 + r;
    const float* p = W + (size_t)nrow * K + col;
    dst[idx] = make_uint2(f2tf(p[0]), f2tf(p[4]));
}

// ================= tf32 tensor-core GEMM, direct-from-global fragments =================
__device__ __forceinline__ void mma8(float* d, const uint4& a, const uint2& b) {
    asm volatile(
        "mma.sync.aligned.m16n8k8.row.col.f32.tf32.tf32.f32 "
        "{%0,%1,%2,%3}, {%4,%5,%6,%7}, {%8,%9}, {%0,%1,%2,%3};\n"
        : "+f"(d[0]), "+f"(d[1]), "+f"(d[2]), "+f"(d[3])
        : "r"(a.x), "r"(a.y), "r"(a.z), "r"(a.w), "r"(b.x), "r"(b.y));
}

__global__ __launch_bounds__(256, 2)
void tgemm_d(const uint4* __restrict__ Af, const uint2* __restrict__ Bf,
             float* __restrict__ C, int N, int K)
{
    const int t    = threadIdx.x;
    const int w    = t >> 5;
    const int lane = t & 31;
    const int g    = lane >> 2;
    const int r    = lane & 3;
    const int wm   = w & 3;
    const int wn   = w >> 2;
    const int bm   = blockIdx.y, bn = blockIdx.x;
    const int kch  = K >> 5;
    const int nks  = K >> 3;

    const uint4* Ap = Af + (size_t)bm * kch * 1024 + (wm * 2) * 32 + lane;
    const uint2* Bp = Bf + (size_t)(bn * 2 + wn) * kch * 1024 + lane;

    float c[2][8][4];
#pragma unroll
    for (int i = 0; i < 2; i++)
#pragma unroll
        for (int j = 0; j < 8; j++)
#pragma unroll
            for (int e = 0; e < 4; e++) c[i][j][e] = 0.f;

    uint4 a0 = Ap[0], a1 = Ap[32];
    uint2 b[8];
#pragma unroll
    for (int j = 0; j < 8; j++) b[j] = Bp[j * 128];

    for (int ks = 0; ks < nks - 1; ks++) {
        int ks1 = ks + 1;
        const uint4* An = Ap + (size_t)ks1 * 256;
        const uint2* Bn = Bp + ((ks1 >> 2) * 1024 + (ks1 & 3) * 32);
        uint4 na0 = An[0];
        uint4 na1 = An[32];
        uint2 nb[8];
#pragma unroll
        for (int j = 0; j < 8; j++) nb[j] = Bn[j * 128];

#pragma unroll
        for (int j = 0; j < 8; j++) {
            mma8(c[0][j], a0, b[j]);
            mma8(c[1][j], a1, b[j]);
        }

        a0 = na0; a1 = na1;
#pragma unroll
        for (int j = 0; j < 8; j++) b[j] = nb[j];
    }
#pragma unroll
    for (int j = 0; j < 8; j++) {
        mma8(c[0][j], a0, b[j]);
        mma8(c[1][j], a1, b[j]);
    }

    float* Cp = C + (size_t)(bm * 128) * N + bn * 128 + wn * 64;
#pragma unroll
    for (int i = 0; i < 2; i++) {
#pragma unroll
        for (int j = 0; j < 8; j++) {
            int row = (wm * 2 + i) * 16 + g;
            int col = j * 8 + r * 2;
            *(float2*)(Cp + (size_t)row * N + col) =
                make_float2(c[i][j][0], c[i][j][1]);
            *(float2*)(Cp + (size_t)(row + 8) * N + col) =
                make_float2(c[i][j][2], c[i][j][3]);
        }
    }
}

// ---------------- RoPE + split into Q,K,V [B,H,S,64] ----------------
__global__ void rope_split(const float* __restrict__ qkv)
{
    int idx = blockIdx.x * blockDim.x + threadIdx.x;
    if (idx >= Bb * Ss * Hh * 32) return;
    int i  = idx & 31;
    int t2 = idx >> 5;
    int h  = t2 % Hh;
    int t3 = t2 / Hh;
    int s  = t3 % Ss;
    int b  = t3 / Ss;

    float inv = exp2f(-(float)(2 * i) * (1.0f / 64.f) * 13.287712379549449f);
    float fr  = (float)s * inv;
    float cs, sn;
    sincosf(fr, &sn, &cs);

    size_t base = ((size_t)(b * Ss + s)) * (3 * Dd) + h * 64 + i;
    float q1 = qkv[base],        q2 = qkv[base + 32];
    float k1 = qkv[base + Dd],   k2 = qkv[base + Dd + 32];
    float v1 = qkv[base + 2*Dd], v2 = qkv[base + 2*Dd + 32];

    size_t ob = ((size_t)((b * Hh + h) * Ss + s)) * 64 + i;
    g_q[ob]      = q1 * cs - q2 * sn;
    g_q[ob + 32] = q2 * cs + q1 * sn;
    g_k[ob]      = k1 * cs - k2 * sn;
    g_k[ob + 32] = k2 * cs + k1 * sn;
    g_v[ob]      = v1;
    g_v[ob + 32] = v2;
}

// ---------------- sliding-window attention: 512 threads, 4 rows/warp ----------------
#define QT 64
#define KT 192          // QT + 2*WIN
#define KST 68          // smem row stride (floats)
#define ATHREADS 512

__global__ __launch_bounds__(ATHREADS, 1)
void attn_kernel()
{
    extern __shared__ float sm[];
    float* Ks = sm;                      // [KT][KST]
    float* Vs = sm + KT * KST;           // [KT][KST]
    float* Qs = sm + 2 * KT * KST;       // [QT][64]

    const int t  = threadIdx.x;
    const int qt = blockIdx.x * QT;
    const int h  = blockIdx.y, b = blockIdx.z;
    const float* Kg = g_k + (size_t)((b * Hh + h) * Ss) * 64;
    const float* Vg = g_v + (size_t)((b * Hh + h) * Ss) * 64;
    const float* Qg = g_q + (size_t)((b * Hh + h) * Ss) * 64;

    for (int i = t; i < KT * 16; i += ATHREADS) {
        int row = i >> 4, c = (i & 15) * 4;
        int g = qt - WIN + row;
        float4 kv = make_float4(0.f, 0.f, 0.f, 0.f);
        float4 vv = make_float4(0.f, 0.f, 0.f, 0.f);
        if (g >= 0 && g < Ss) {
            kv = *(const float4*)(Kg + (size_t)g * 64 + c);
            vv = *(const float4*)(Vg + (size_t)g * 64 + c);
        }
        *(float4*)&Ks[row * KST + c] = kv;
        *(float4*)&Vs[row * KST + c] = vv;
    }
    for (int i = t; i < QT * 16; i += ATHREADS) {
        int row = i >> 4, c = (i & 15) * 4;
        float4 qv = *(const float4*)(Qg + (size_t)(qt + row) * 64 + c);
        qv.x *= 0.125f; qv.y *= 0.125f; qv.z *= 0.125f; qv.w *= 0.125f;
        *(float4*)&Qs[row * 64 + c] = qv;
    }
    __syncthreads();

    const int w = t >> 5, lane = t & 31;   // 16 warps, 4 rows each
    for (int r = 0; r < 4; r++) {
        int ql = w * 4 + r;
        float m = -1e30f, l = 0.f, acc0 = 0.f, acc1 = 0.f;
        int cbase = (ql >> 5) * 32;   // window [ql, ql+128] covered by exactly 5 chunks
#pragma unroll
        for (int c = 0; c < 5; c++) {
            int j0 = cbase + c * 32;
            int jl = j0 + lane;
            int g  = qt - WIN + jl;
            float sum = 0.f;
            {
                const float4* kr = (const float4*)&Ks[jl * KST];
                const float4* qr = (const float4*)&Qs[ql * 64];
#pragma unroll
                for (int d = 0; d < 16; d++) {
                    float4 kq = kr[d], qq = qr[d];
                    sum += qq.x * kq.x + qq.y * kq.y + qq.z * kq.z + qq.w * kq.w;
                }
            }
            bool valid = (g >= 0) && (g < Ss) && (jl >= ql) && (jl <= ql + 2 * WIN);
            float s = valid ? sum : -3.0e38f;

            float cm = s;
#pragma unroll
            for (int o = 16; o; o >>= 1) cm = fmaxf(cm, __shfl_xor_sync(0xffffffffu, cm, o));
            float nm   = fmaxf(m, cm);
            float corr = __expf(m - nm);
            float p    = __expf(s - nm);
            float ps   = p;
#pragma unroll
            for (int o = 16; o; o >>= 1) ps += __shfl_xor_sync(0xffffffffu, ps, o);
            l = l * corr + ps;
            acc0 *= corr; acc1 *= corr;
#pragma unroll
            for (int j = 0; j < 32; j++) {
                float pj = __shfl_sync(0xffffffffu, p, j);
                acc0 += pj * Vs[(j0 + j) * KST + lane];
                acc1 += pj * Vs[(j0 + j) * KST + lane + 32];
            }
            m = nm;
        }
        float invl = 1.f / l;

        // fragment-order tf32 store into g_af2 (A operand of the Wo GEMM)
        int row = b * Ss + qt + ql;
        int bm = row >> 7, mt = (row >> 4) & 7, gg = row & 7, hi = (row >> 3) & 1;
        int kc  = (h * 64 + lane) >> 5;
        int kt  = (lane >> 3) & 3;
        int rr  = lane & 3;
        int ch  = (lane >> 2) & 1;
        int reg = hi + 2 * ch;
        size_t off = ((size_t)bm * (Dd / 32) + kc) * 4096
                   + (size_t)((kt * 8 + mt) * 32 + (gg * 4 + rr)) * 4 + reg;
        g_af2[off]        = f2tf(acc0 * invl);
        g_af2[off + 4096] = f2tf(acc1 * invl);
    }
}

// ---------------- launch ----------------
extern "C" void kernel_launch(void* const* d_in, const int* in_sizes, int n_in,
                              void* d_out, int out_size)
{
    const float* hidden = (const float*)d_in[0];   // [B,S,D]
    const float* Wqkv   = (const float*)d_in[1];   // [3D, D]
    const float* Wo     = (const float*)d_in[2];   // [D, D]
    float* out = (float*)d_out;

    float *qkv;
    unsigned *af1, *af2, *bf1, *bf2;
    cudaGetSymbolAddress((void**)&qkv, g_qkv);
    cudaGetSymbolAddress((void**)&af1, g_af1);
    cudaGetSymbolAddress((void**)&af2, g_af2);
    cudaGetSymbolAddress((void**)&bf1, g_bf1);
    cudaGetSymbolAddress((void**)&bf2, g_bf2);

    // 0) one-shot reformats into fragment order (tf32)
    fmt_a<<<(Bb * Ss * Dd / 4) / 256, 256>>>(hidden, (uint4*)af1, Dd);
    fmt_b<<<(3 * Dd * Dd / 2) / 256, 256>>>(Wqkv, (uint2*)bf1, Dd);
    fmt_b<<<(Dd * Dd / 2) / 256, 256>>>(Wo, (uint2*)bf2, Dd);

    // 1) QKV projection: [4096,768] x [2304,768]^T -> [4096,2304]
    tgemm_d<<<dim3(3 * Dd / 128, Bb * Ss / 128), 256>>>((const uint4*)af1,
                                                        (const uint2*)bf1,
                                                        qkv, 3 * Dd, Dd);
    // 2) RoPE + split
    rope_split<<<(Bb * Ss * Hh * 32 + 255) / 256, 256>>>(qkv);

    // 3) sliding-window attention -> g_af2 (fragment order)
    const int SMEM = (2 * KT * KST + QT * 64) * (int)sizeof(float);
    cudaFuncSetAttribute(attn_kernel, cudaFuncAttributeMaxDynamicSharedMemorySize, SMEM);
    attn_kernel<<<dim3(Ss / QT, Hh, Bb), ATHREADS, SMEM>>>();

    // 4) output projection: [4096,768] x [768,768]^T -> [4096,768]
    tgemm_d<<<dim3(Dd / 128, Bb * Ss / 128), 256>>>((const uint4*)af2,
                                                    (const uint2*)bf2,
                                                    out, Dd, Dd);
}